// round 7
// baseline (speedup 1.0000x reference)
#include <cuda_runtime.h>
#include <math.h>

#define KKEY   2048
#define CFEAT  128
#define M_GRID 216
#define NPROP  48
#define NPTS   (NPROP*M_GRID)      // 10368 per batch
#define NTOT   (2*NPTS)            // 20736
#define QDIM   (128*M_GRID)        // 27648
#define KSPLIT 108
#define KCHUNK 256

typedef unsigned long long ull;

__device__ __forceinline__ ull pack2(float lo, float hi) {
    ull r; asm("mov.b64 %0, {%1, %2};" : "=l"(r) : "f"(lo), "f"(hi)); return r;
}
__device__ __forceinline__ ull ffma2(ull a, ull b, ull c) {
    ull d; asm("fma.rn.f32x2 %0, %1, %2, %3;" : "=l"(d) : "l"(a), "l"(b), "l"(c)); return d;
}
__device__ __forceinline__ float2 unpack2(ull v) {
    float2 f; asm("mov.b64 {%0, %1}, %2;" : "=f"(f.x), "=f"(f.y) : "l"(v)); return f;
}
__device__ __forceinline__ unsigned f2tf32(float v) {
    unsigned u; asm("cvt.rna.tf32.f32 %0, %1;" : "=r"(u) : "f"(v)); return u;
}
__device__ __forceinline__ void mma_tf32(float d[4], const unsigned a[4],
                                         const unsigned b0, const unsigned b1) {
    asm("mma.sync.aligned.m16n8k8.row.col.f32.tf32.tf32.f32 "
        "{%0,%1,%2,%3}, {%4,%5,%6,%7}, {%8,%9}, {%0,%1,%2,%3};"
        : "+f"(d[0]), "+f"(d[1]), "+f"(d[2]), "+f"(d[3])
        : "r"(a[0]), "r"(a[1]), "r"(a[2]), "r"(a[3]), "r"(b0), "r"(b1));
}

// ---------------- scratch ----------------
__device__ float  g_new_xyz[NTOT*3];
__device__ float  g_pre[2*2*KKEY*64];        // [scale][b][k][interleaved o]
__device__ float4 g_rel1[NTOT*32];           // {rx,ry,rz, bitcast k}
__device__ float4 g_rel0[NTOT*16];
__device__ float  g_pooled[2*NPROP*QDIM];    // 96 x 27648, q = co*216+mm
__device__ float  g_partial[KSPLIT*96*256];

// ---------------- kernel A ----------------
__global__ void __launch_bounds__(256) kA(const float* __restrict__ prop,
                                          const float* __restrict__ gnoise) {
    int t = blockIdx.x*256 + threadIdx.x;
    if (t >= NTOT) return;
    int b = t / NPTS, r = t % NPTS;
    int n = r / M_GRID, mm = r % M_GRID;
    const float* p = prop + (size_t)(b*NPROP + n)*7;
    const float* g = gnoise + ((size_t)(b*NPROP + n)*M_GRID + mm)*3;
    float gx = g[0]*p[3], gy = g[1]*p[4], gz = g[2]*p[5];
    float c = cosf(p[6]), s = sinf(p[6]);
    float* o = g_new_xyz + (size_t)t*3;
    o[0] = c*gx - s*gy + p[0];
    o[1] = s*gx + c*gy + p[1];
    o[2] = gz + p[2];
}

// ---------------- kernel B: pre[k][o] = W0[:,3:] . feats[:,k] ----------------
__global__ void __launch_bounds__(256) kB(const float* __restrict__ feats,
                                          const float* __restrict__ w0,
                                          const float* __restrict__ w1) {
    __shared__ float Ws[CFEAT*64];
    __shared__ float fs[CFEAT*32];
    int sb = blockIdx.y; int sc = sb >> 1, b = sb & 1;
    const float* W = sc ? w1 : w0;
    for (int i = threadIdx.x; i < CFEAT*64; i += 256) {
        int c = i >> 6, o = i & 63;
        Ws[i] = W[o*131 + 3 + c];
    }
    int kbase = blockIdx.x * 32;
    const float* fb = feats + (size_t)b*CFEAT*KKEY + kbase;
    for (int i = threadIdx.x; i < CFEAT*8; i += 256) {
        int c = i >> 3, q = i & 7;
        *(float4*)(fs + c*32 + q*4) = *(const float4*)(fb + (size_t)c*KKEY + q*4);
    }
    __syncthreads();

    int o  = threadIdx.x & 63;
    int kk = threadIdx.x >> 6;
    ull acc0 = 0, acc1 = 0, acc2 = 0, acc3 = 0;
    #pragma unroll 4
    for (int c = 0; c < CFEAT; c++) {
        float w = Ws[c*64 + o];
        ull wd = pack2(w, w);
        const ull* f = (const ull*)(fs + c*32 + kk*8);
        acc0 = ffma2(wd, f[0], acc0);
        acc1 = ffma2(wd, f[1], acc1);
        acc2 = ffma2(wd, f[2], acc2);
        acc3 = ffma2(wd, f[3], acc3);
    }
    size_t base = ((size_t)(sc*2 + b)*KKEY + kbase + kk*8) << 6;
    int oi = ((o & 31) << 1) + (o >> 5);
    float2 u;
    u = unpack2(acc0); g_pre[base + oi] = u.x; g_pre[base + 64 + oi] = u.y;
    u = unpack2(acc1); g_pre[base + 128 + oi] = u.x; g_pre[base + 192 + oi] = u.y;
    u = unpack2(acc2); g_pre[base + 256 + oi] = u.x; g_pre[base + 320 + oi] = u.y;
    u = unpack2(acc3); g_pre[base + 384 + oi] = u.x; g_pre[base + 448 + oi] = u.y;
}

// ---------------- kernel Q: ball query -> padded idx + rel coords ----------
__global__ void __launch_bounds__(256) kQ(const float* __restrict__ kxyzg) {
    __shared__ float kp[KKEY*3];               // interleaved xyz
    __shared__ int idx1s[8][32], idx0s[8][16];

    const int b = blockIdx.x / 1296;
    const float* kb = kxyzg + (size_t)b*KKEY*3;
    for (int i = threadIdx.x; i < KKEY*3; i += 256) kp[i] = kb[i];
    __syncthreads();

    const int w = threadIdx.x >> 5, lane = threadIdx.x & 31;
    const int p = blockIdx.x*8 + w;
    const float px = g_new_xyz[(size_t)p*3], py = g_new_xyz[(size_t)p*3+1],
                pz = g_new_xyz[(size_t)p*3+2];
    const float pn = fmaf(px,px, fmaf(py,py, pz*pz));

    const float R0 = 0.8f*0.8f, R1 = 1.6f*1.6f;
    int* l1 = idx1s[w];
    int* l0 = idx0s[w];
    int c0 = 0, c1 = 0;
    const unsigned lt = (1u << lane) - 1u;
    for (int base = 0; base < KKEY; base += 32) {
        int k = base + lane;
        float kx = kp[3*k], ky = kp[3*k+1], kz = kp[3*k+2];
        float kn  = fmaf(kx,kx, fmaf(ky,ky, kz*kz));
        float dot = fmaf(px,kx, fmaf(py,ky, pz*kz));
        float d2  = fmaf(-2.f, dot, pn + kn);
        bool v1 = d2 < R1, v0 = d2 < R0;
        unsigned m1 = __ballot_sync(0xffffffffu, v1);
        unsigned m0 = __ballot_sync(0xffffffffu, v0);
        if (c1 < 32 && m1) {
            if (v1) { int rk = c1 + __popc(m1 & lt); if (rk < 32) l1[rk] = k; }
            c1 = min(32, c1 + __popc(m1));
        }
        if (c0 < 16 && m0) {
            if (v0) { int rk = c0 + __popc(m0 & lt); if (rk < 16) l0[rk] = k; }
            c0 = min(16, c0 + __popc(m0));
        }
        if (c0 >= 16 && c1 >= 32) break;
    }
    __syncwarp();
    if (c1 == 0) { if (lane == 0) l1[0] = 0; c1 = 1; }
    if (c0 == 0) { if (lane == 0) l0[0] = 0; c0 = 1; }
    __syncwarp();
    {
        int f1 = l1[0], f0 = l0[0];
        if (lane >= c1) l1[lane] = f1;
        if (lane < 16 && lane >= c0) l0[lane] = f0;
    }
    __syncwarp();

    {
        int k = l1[lane];
        g_rel1[(size_t)p*32 + lane] =
            make_float4(kp[3*k]-px, kp[3*k+1]-py, kp[3*k+2]-pz, __int_as_float(k));
        if (lane < 16) {
            int k0 = l0[lane];
            g_rel0[(size_t)p*16 + lane] =
                make_float4(kp[3*k0]-px, kp[3*k0+1]-py, kp[3*k0+2]-pz, __int_as_float(k0));
        }
    }
}

// ---------------- kernel C2: 2 points/warp, layer0 + tf32 MMA + maxpool ----
// 256 threads = 8 warps = 16 points/block.
// MMA k-dim permutation: j' = 2*(o&31) + (o>>5), so layer-0 writes (va,vb)
// as one STS.64 at hw[row*68 + 2*lane]. b-table built under the same perm.
// dyn smem words:
//  wpk[2][8kt][8nt][32] uint2            0     .. 8192
//  wxyz[2][3][64]                        8192  .. 8576
//  b0s[128]                              8576  .. 8704
//  b1s[128]                              8704  .. 8832
//  hw[8 warps][32 rows][68]              8832  .. 26240
#define KC2_SMEM_WORDS 26240
#define OFF2_WXYZ 8192
#define OFF2_B0   8576
#define OFF2_B1   8704
#define OFF2_HW   8832

__global__ void __launch_bounds__(256, 2) kC2(
    const float* __restrict__ w00, const float* __restrict__ b00,
    const float* __restrict__ w01, const float* __restrict__ b01,
    const float* __restrict__ w10, const float* __restrict__ b10,
    const float* __restrict__ w11, const float* __restrict__ b11)
{
    extern __shared__ float sm[];
    uint2*    wpk  = (uint2*)sm;               // [sc][kt][nt][lane]
    float*    wxyz = sm + OFF2_WXYZ;
    float*    b0s  = sm + OFF2_B0;
    float*    b1s  = sm + OFF2_B1;
    unsigned* hwg  = (unsigned*)(sm + OFF2_HW);

    // b-table with permuted k-dim: position jp -> original j
    for (int i = threadIdx.x; i < 2*8*8*32; i += 256) {
        int lane2 = i & 31, nt = (i >> 5) & 7, kt = (i >> 8) & 7, sc = i >> 11;
        int gid2 = lane2 >> 2, tig2 = lane2 & 3;
        const float* W1 = sc ? w11 : w01;
        int o = nt*8 + gid2;
        int jp0 = kt*8 + tig2, jp1 = jp0 + 4;
        int j0 = (jp0 & 1) ? 32 + (jp0 >> 1) : (jp0 >> 1);
        int j1 = (jp1 & 1) ? 32 + (jp1 >> 1) : (jp1 >> 1);
        wpk[i] = make_uint2(f2tf32(W1[o*64 + j0]), f2tf32(W1[o*64 + j1]));
    }
    for (int i = threadIdx.x; i < 2*3*64; i += 256) {
        int sc = i / 192, t = i % 192, d = t / 64, o = t % 64;
        wxyz[i] = (sc ? w10 : w00)[o*131 + d];
    }
    if (threadIdx.x < 256) {
        int sc = (threadIdx.x >> 6) & 1, o = threadIdx.x & 63;
        if (threadIdx.x < 128) b0s[threadIdx.x] = (sc ? b10 : b00)[o];
        else                   b1s[threadIdx.x - 128] = (sc ? b11 : b01)[o];
    }
    __syncthreads();

    const int w = threadIdx.x >> 5, lane = threadIdx.x & 31;
    const int gid = lane >> 2, tig = lane & 3;
    const int p0 = blockIdx.x*16 + w*2;        // points p0, p0+1 (same batch)
    const int b  = p0 / NPTS;

    unsigned* hw = hwg + w*2176;               // [row 0..31][j'], pitch 68

    #pragma unroll
    for (int sc = 0; sc < 2; sc++) {
        const int NPASS = sc ? 2 : 1;
        const float* preb = g_pre + ((size_t)(sc*2 + b)*KKEY << 6);
        const uint2* wps = wpk + sc*2048;
        const float* wx = wxyz + sc*192;
        const float bias0a = b0s[sc*64 + lane],  bias0b = b0s[sc*64 + lane + 32];
        const float wxa0 = wx[lane],    wxa1 = wx[64+lane],  wxa2 = wx[128+lane];
        const float wxb0 = wx[lane+32], wxb1 = wx[96+lane],  wxb2 = wx[160+lane];

        float cm0[2][8], cm1[2][8];
        #pragma unroll
        for (int q = 0; q < 2; q++)
            #pragma unroll
            for (int nt = 0; nt < 8; nt++) { cm0[q][nt] = -3.4e38f; cm1[q][nt] = -3.4e38f; }

        for (int pass = 0; pass < NPASS; pass++) {
            // ---- layer 0: 2 points x 16 samples -> hw rows [q*16+s] ----
            #pragma unroll
            for (int q = 0; q < 2; q++) {
                const float4* relb = sc
                    ? (g_rel1 + (size_t)(p0+q)*32 + pass*16)
                    : (g_rel0 + (size_t)(p0+q)*16);
                #pragma unroll
                for (int s0 = 0; s0 < 16; s0 += 4) {
                    float4 rv[4];
                    float2 pr[4];
                    #pragma unroll
                    for (int s = 0; s < 4; s++) {
                        rv[s] = __ldg(relb + s0 + s);    // uniform addr -> broadcast
                        int k = __float_as_int(rv[s].w);
                        pr[s] = *(const float2*)(preb + ((size_t)k << 6) + (lane << 1));
                    }
                    #pragma unroll
                    for (int s = 0; s < 4; s++) {
                        float va = pr[s].x + bias0a;
                        va = fmaf(rv[s].x, wxa0, va);
                        va = fmaf(rv[s].y, wxa1, va);
                        va = fmaf(rv[s].z, wxa2, va);
                        float vb = pr[s].y + bias0b;
                        vb = fmaf(rv[s].x, wxb0, vb);
                        vb = fmaf(rv[s].y, wxb1, vb);
                        vb = fmaf(rv[s].z, wxb2, vb);
                        unsigned pa = f2tf32(fmaxf(va, 0.f));
                        unsigned pb = f2tf32(fmaxf(vb, 0.f));
                        *(uint2*)(hw + (q*16 + s0 + s)*68 + (lane << 1)) =
                            make_uint2(pa, pb);
                    }
                }
            }
            __syncwarp();

            // ---- layer 1: mt=2 points share each b-fragment ----
            float acc[2][8][4];
            #pragma unroll
            for (int q = 0; q < 2; q++)
                #pragma unroll
                for (int nt = 0; nt < 8; nt++)
                    acc[q][nt][0] = acc[q][nt][1] = acc[q][nt][2] = acc[q][nt][3] = 0.f;
            #pragma unroll
            for (int kt = 0; kt < 8; kt++) {
                unsigned a[2][4];
                #pragma unroll
                for (int q = 0; q < 2; q++) {
                    const unsigned* hrow = hw + (q*16 + gid)*68 + kt*8 + tig;
                    a[q][0] = hrow[0];
                    a[q][1] = hrow[8*68];
                    a[q][2] = hrow[4];
                    a[q][3] = hrow[8*68 + 4];
                }
                const uint2* wrow = wps + kt*256 + lane;
                #pragma unroll
                for (int nt = 0; nt < 8; nt++) {
                    uint2 bb = wrow[nt*32];
                    mma_tf32(acc[0][nt], a[0], bb.x, bb.y);
                    mma_tf32(acc[1][nt], a[1], bb.x, bb.y);
                }
            }
            #pragma unroll
            for (int q = 0; q < 2; q++)
                #pragma unroll
                for (int nt = 0; nt < 8; nt++) {
                    cm0[q][nt] = fmaxf(cm0[q][nt], fmaxf(acc[q][nt][0], acc[q][nt][2]));
                    cm1[q][nt] = fmaxf(cm1[q][nt], fmaxf(acc[q][nt][1], acc[q][nt][3]));
                }
            __syncwarp();
        }

        // reduce across row-groups (lane bits 2..4)
        #pragma unroll
        for (int off = 4; off <= 16; off <<= 1) {
            #pragma unroll
            for (int q = 0; q < 2; q++)
                #pragma unroll
                for (int nt = 0; nt < 8; nt++) {
                    cm0[q][nt] = fmaxf(cm0[q][nt], __shfl_xor_sync(0xffffffffu, cm0[q][nt], off));
                    cm1[q][nt] = fmaxf(cm1[q][nt], __shfl_xor_sync(0xffffffffu, cm1[q][nt], off));
                }
        }
        if (gid == 0) {
            #pragma unroll
            for (int q = 0; q < 2; q++) {
                int rp = (p0 + q) % NPTS;
                int n = rp / M_GRID, mm = rp % M_GRID;
                size_t rowb = (size_t)(b*NPROP + n)*QDIM + (size_t)sc*64*M_GRID + mm;
                #pragma unroll
                for (int nt = 0; nt < 8; nt++) {
                    int o0 = nt*8 + tig*2;
                    float v0 = fmaxf(cm0[q][nt] + b1s[sc*64 + o0],     0.f);
                    float v1 = fmaxf(cm1[q][nt] + b1s[sc*64 + o0 + 1], 0.f);
                    g_pooled[rowb + (size_t)o0*M_GRID]     = v0;
                    g_pooled[rowb + (size_t)(o0+1)*M_GRID] = v1;
                }
            }
        }
    }
}

// ---------------- kernel D: K-split GEMM, 4x8 thread tile -------------------
#define KD_KT 16
#define XSP 36
#define WSP 260
__global__ void __launch_bounds__(256) kD(const float* __restrict__ w0) {
    __shared__ float xs[2][KD_KT*XSP];
    __shared__ float ws[2][KD_KT*WSP];
    const int tid = threadIdx.x;
    const int tx = tid & 31, ty = tid >> 5;
    const int rowbase = blockIdx.y * 32;
    const int kg0 = blockIdx.z * KCHUNK;

    const int xrow = tid >> 3, xk = (tid & 7) << 1;
    const int wcol = tid >> 2, wk = (tid & 3) << 2;

    const float* xg = g_pooled + (size_t)(rowbase + xrow)*QDIM + kg0 + xk;
    const float* wg0 = w0 + (size_t)(wcol      )*QDIM + kg0 + wk;
    const float* wg1 = w0 + (size_t)(wcol +  64)*QDIM + kg0 + wk;
    const float* wg2 = w0 + (size_t)(wcol + 128)*QDIM + kg0 + wk;
    const float* wg3 = w0 + (size_t)(wcol + 192)*QDIM + kg0 + wk;

    float2 xv = *(const float2*)xg;
    float4 wv0 = *(const float4*)wg0;
    float4 wv1 = *(const float4*)wg1;
    float4 wv2 = *(const float4*)wg2;
    float4 wv3 = *(const float4*)wg3;

    float acc[4][8] = {};
    const int NT = KCHUNK / KD_KT;      // 16
    for (int t = 0; t < NT; t++) {
        float* xsc = xs[t & 1];
        float* wsc = ws[t & 1];
        xsc[(xk  )*XSP + xrow] = xv.x;
        xsc[(xk+1)*XSP + xrow] = xv.y;
        #pragma unroll
        for (int j = 0; j < 4; j++) {
            wsc[(wk+j)*WSP + wcol      ] = ((const float*)&wv0)[j];
            wsc[(wk+j)*WSP + wcol +  64] = ((const float*)&wv1)[j];
            wsc[(wk+j)*WSP + wcol + 128] = ((const float*)&wv2)[j];
            wsc[(wk+j)*WSP + wcol + 192] = ((const float*)&wv3)[j];
        }
        __syncthreads();
        if (t + 1 < NT) {
            int d = (t + 1) * KD_KT;
            xv  = *(const float2*)(xg + d);
            wv0 = *(const float4*)(wg0 + d);
            wv1 = *(const float4*)(wg1 + d);
            wv2 = *(const float4*)(wg2 + d);
            wv3 = *(const float4*)(wg3 + d);
        }
        #pragma unroll
        for (int kk = 0; kk < KD_KT; kk++) {
            float4 xq = *(const float4*)(xsc + kk*XSP + ty*4);
            float4 wa = *(const float4*)(wsc + kk*WSP + tx*4);
            float4 wb = *(const float4*)(wsc + kk*WSP + 128 + tx*4);
            const float xr[4] = {xq.x, xq.y, xq.z, xq.w};
            const float wc[8] = {wa.x, wa.y, wa.z, wa.w, wb.x, wb.y, wb.z, wb.w};
            #pragma unroll
            for (int i = 0; i < 4; i++)
                #pragma unroll
                for (int j = 0; j < 8; j++)
                    acc[i][j] = fmaf(xr[i], wc[j], acc[i][j]);
        }
        __syncthreads();
    }
    #pragma unroll
    for (int i = 0; i < 4; i++) {
        int row = rowbase + ty*4 + i;
        float* pp = g_partial + ((size_t)blockIdx.z*96 + row)*256;
        *(float4*)(pp + tx*4)       = make_float4(acc[i][0], acc[i][1], acc[i][2], acc[i][3]);
        *(float4*)(pp + 128 + tx*4) = make_float4(acc[i][4], acc[i][5], acc[i][6], acc[i][7]);
    }
}

// ---------------- kernel E: reduce + relu + 256x256 GEMM + relu ------------
__global__ void __launch_bounds__(256) kE(const float* __restrict__ rb0,
                                          const float* __restrict__ rw1,
                                          const float* __restrict__ rb1,
                                          float* __restrict__ out) {
    __shared__ float h2s[256];
    __shared__ float w1s[256*33];
    const int row = blockIdx.x;
    const int o = threadIdx.x;
    float s = rb0[o];
    #pragma unroll 4
    for (int ks = 0; ks < KSPLIT; ks++)
        s += g_partial[((size_t)ks*96 + row)*256 + o];
    h2s[o] = fmaxf(s, 0.f);
    __syncthreads();

    float acc = rb1[o];
    for (int jt = 0; jt < 256; jt += 32) {
        for (int i = threadIdx.x; i < 8192; i += 256) {
            int oo = i >> 5, jj = i & 31;
            w1s[oo*33 + jj] = rw1[(size_t)oo*256 + jt + jj];
        }
        __syncthreads();
        #pragma unroll
        for (int jj = 0; jj < 32; jj++)
            acc = fmaf(h2s[jt + jj], w1s[o*33 + jj], acc);
        __syncthreads();
    }
    out[(size_t)row*256 + o] = fmaxf(acc, 0.f);
}

// ---------------- launch ----------------
extern "C" void kernel_launch(void* const* d_in, const int* in_sizes, int n_in,
                              void* d_out, int out_size) {
    const float* proposals = (const float*)d_in[0];
    const float* kxyz      = (const float*)d_in[1];
    const float* kfeat     = (const float*)d_in[2];
    const float* gnoise    = (const float*)d_in[3];
    const float* w00 = (const float*)d_in[4];
    const float* b00 = (const float*)d_in[5];
    const float* w01 = (const float*)d_in[6];
    const float* b01 = (const float*)d_in[7];
    const float* w10 = (const float*)d_in[8];
    const float* b10 = (const float*)d_in[9];
    const float* w11 = (const float*)d_in[10];
    const float* b11 = (const float*)d_in[11];
    const float* rw0 = (const float*)d_in[12];
    const float* rb0 = (const float*)d_in[13];
    const float* rw1 = (const float*)d_in[14];
    const float* rb1 = (const float*)d_in[15];
    float* out = (float*)d_out;

    cudaFuncSetAttribute(kC2, cudaFuncAttributeMaxDynamicSharedMemorySize,
                         KC2_SMEM_WORDS * 4);

    kA<<<(NTOT + 255)/256, 256>>>(proposals, gnoise);
    kB<<<dim3(KKEY/32, 4), 256>>>(kfeat, w00, w10);
    kQ<<<NTOT/8, 256>>>(kxyz);
    kC2<<<NTOT/16, 256, KC2_SMEM_WORDS * 4>>>(w00, b00, w01, b01,
                                              w10, b10, w11, b11);
    kD<<<dim3(1, 96/32, KSPLIT), 256>>>(rw0);
    kE<<<96, 256>>>(rb0, rw1, rb1, out);
}